// round 10
// baseline (speedup 1.0000x reference)
#include <cuda_runtime.h>
#include <cstdint>

#define NBLOCKS   128
#define NTHREADS  256
#define BB        64
#define HH        1024
#define II        256
#define SS        512
#define OO        256
#define KTOT      1280

typedef unsigned long long ull;

// ---------------- device scratch ----------------
__device__ float g_xt[SS * II * BB];      // x: [t][kp 128][b 64][2]
__device__ float g_hx[2][HH * BB];        // h exchange: [parity][kp 512][b 64][2]

// ---------------- grid barrier ----------------
__device__ unsigned g_bar_count = 0;
__device__ unsigned g_bar_gen   = 0;

__device__ __forceinline__ void grid_barrier(unsigned base_gen, unsigned step) {
    __syncthreads();
    if (threadIdx.x == 0) {
        __threadfence();
        unsigned prev = atomicAdd(&g_bar_count, 1u);
        if (prev == NBLOCKS - 1) {
            g_bar_count = 0;
            __threadfence();
            atomicAdd(&g_bar_gen, 1u);
        } else {
            while (*(volatile unsigned*)&g_bar_gen - base_gen < step) { }
        }
        __threadfence();
    }
    __syncthreads();
}

// ---------------- cp.async ----------------
__device__ __forceinline__ void cp_async16(uint32_t dst, const void* src) {
    asm volatile("cp.async.cg.shared.global [%0], [%1], 16;" :: "r"(dst), "l"(src));
}
__device__ __forceinline__ void cp_commit() {
    asm volatile("cp.async.commit_group;" ::: "memory");
}
template <int N>
__device__ __forceinline__ void cp_wait() {
    asm volatile("cp.async.wait_group %0;" :: "n"(N) : "memory");
}

// ---------------- f32x2 helpers ----------------
#define LDSV2(a, b, addr) \
    asm volatile("ld.shared.v2.u64 {%0,%1},[%2];" : "=l"(a), "=l"(b) : "r"(addr))
#define FMA2(d, x, y) \
    asm volatile("fma.rn.f32x2 %0,%1,%2,%0;" : "+l"(d) : "l"(x), "l"(y))
#define UNPK(lo, hi, v) \
    asm volatile("mov.b64 {%0,%1},%2;" : "=f"(lo), "=f"(hi) : "l"(v))

// ---------------- smem layout (bytes) ----------------
//   panels[4] : 4 * 8192  =  32768   ([kp 0..63][b 0..15][2], 2-bit XOR swizzle)
//   w_t       : 640*256   = 163840   ([kp][n 0..31][2], 2-bit XOR swizzle)
//   red       : 8*544*4   =  17408
//   bias      : 128
static constexpr int OFF_PAN  = 0;
static constexpr int PAN_BYTES = 8192;
static constexpr int OFF_WT   = 4 * PAN_BYTES;            // 32768
static constexpr int OFF_RED  = OFF_WT + 640 * 256;       // 196608
static constexpr int OFF_BIAS = OFF_RED + 17408;          // 214016
static constexpr int SMEM_BYTES = OFF_BIAS + 128;         // 214144

// Stage one 8KB panel (64 rows x 128B) from gmem rows of 512B stride.
// srcRowBase points at this CTA's 128B sub-row of global row 0 (float units).
__device__ __forceinline__ void stage_panel(const float* __restrict__ srcRowBase,
                                            uint32_t dst) {
#pragma unroll
    for (int j = 0; j < 2; ++j) {
        int e   = threadIdx.x * 2 + j;     // chunk 0..511
        int row = e >> 3;                  // kp_local 0..63
        int cc  = e & 7;                   // chunk within row
        cp_async16(dst + (uint32_t)(row * 128) + (uint32_t)((cc * 16) ^ ((row & 3) * 16)),
                   srcRowBase + (size_t)row * 128 + cc * 4);
    }
    cp_commit();
}

// One 64-kp panel. Thread covers kp_local = kc, kc+32; tile 8b x 8n.
__device__ __forceinline__ void compute_panel(uint32_t pan, uint32_t wt,
                                              int kp_base, int bp, int np, int kc,
                                              ull acc[64]) {
#pragma unroll
    for (int kk = 0; kk < 2; ++kk) {
        int kpl = kc + 32 * kk;
        int kpg = kp_base + kpl;
        uint32_t hrow = pan + (uint32_t)(kpl * 128);
        uint32_t wrow = wt + (uint32_t)(kpg * 256);
        uint32_t hx = (uint32_t)((kpl & 3) * 16);
        uint32_t wx = (uint32_t)((kpg & 3) * 16);
        ull h[8], w[8];
#pragma unroll
        for (int i = 0; i < 4; ++i)
            LDSV2(h[2 * i], h[2 * i + 1], hrow + (((uint32_t)(bp * 64 + i * 16)) ^ hx));
#pragma unroll
        for (int i = 0; i < 4; ++i)
            LDSV2(w[2 * i], w[2 * i + 1], wrow + (((uint32_t)(np * 64 + i * 16)) ^ wx));
#pragma unroll
        for (int I = 0; I < 8; ++I)
#pragma unroll
            for (int J = 0; J < 8; ++J)
                FMA2(acc[I * 8 + J], h[I], w[J]);
    }
}

__global__ void __launch_bounds__(NTHREADS, 1)
rnn_persistent_kernel(const float* __restrict__ wih,
                      const float* __restrict__ whh,
                      const float* __restrict__ bias,
                      float* __restrict__ hstates)   // [S+1][B][H]
{
    extern __shared__ float smem_f[];
    const uint32_t sbase = (uint32_t)__cvta_generic_to_shared(smem_f);
    const uint32_t u_wt  = sbase + OFF_WT;
    float* red_f  = smem_f + OFF_RED / 4;
    float* bias_s = smem_f + OFF_BIAS / 4;

    const int tid  = threadIdx.x;
    const int lane = tid & 31;
    const int warp = tid >> 5;
    const int np   = lane & 3;                // n-position (8n each)
    const int bp   = (lane >> 2) & 1;         // b-position (8b each)
    const int kc   = warp * 4 + (lane >> 3);  // k-lane 0..31
    const int ng   = blockIdx.x & 31;         // 32 n-groups of 32
    const int bg   = blockIdx.x >> 5;         // 4 b-groups of 16
    const int n0   = ng * 32;
    const int b0   = bg * 16;

    // Fill weights: w(k, n0+n) -> [kp][n][2] with chunk swizzle c ^= (kp&3).
    for (int i = tid; i < 32 * KTOT; i += NTHREADS) {
        int n = i / KTOT;                     // 0..31
        int k = i - n * KTOT;                 // coalesced in k
        float v = (k < HH) ? whh[(size_t)(n0 + n) * HH + k]
                           : wih[(size_t)(n0 + n) * II + (k - HH)];
        int kp = k >> 1, par = k & 1;
        uint32_t byteoff = (uint32_t)(kp * 256)
                         + ((uint32_t)((n >> 1) * 16) ^ (uint32_t)((kp & 3) * 16))
                         + (uint32_t)((n & 1) * 8 + par * 4);
        *(float*)((char*)smem_f + OFF_WT + byteoff) = v;
    }
    if (tid < 32) bias_s[tid] = bias[n0 + tid];

    unsigned base_gen = *(volatile unsigned*)&g_bar_gen;

    // Prologue: prefetch the two x-panels for t=0 into slots 0, 1.
    stage_panel(g_xt + 0 * 8192 + bg * 32, sbase + OFF_PAN + 0 * PAN_BYTES);
    stage_panel(g_xt + 1 * 8192 + bg * 32, sbase + OFF_PAN + 1 * PAN_BYTES);
    __syncthreads();   // weights/bias ready

    unsigned bstep = 1;

#pragma unroll 1
    for (int t = 0; t < SS; ++t) {
        const float* hx_src = g_hx[t & 1] + bg * 32;
        ull acc[64];
#pragma unroll
        for (int i = 0; i < 64; ++i) acc[i] = 0ull;

        // Panels: p0,p1 = x (kp_base 512, 576); p2..p9 = h (kp_base 0..448).
#pragma unroll 1
        for (int p = 0; p < 10; ++p) {
            int next = p + 2;
            uint32_t nslot = sbase + OFF_PAN + (uint32_t)((2 * t + next) & 3) * PAN_BYTES;
            if (next < 10) {
                stage_panel(hx_src + (size_t)(next - 2) * 8192, nslot);
            } else {
                int tn = (t + 1 < SS) ? (t + 1) : t;
                stage_panel(g_xt + (size_t)tn * 16384 + (size_t)(next - 10) * 8192 + bg * 32,
                            nslot);
            }
            cp_wait<2>();
            __syncthreads();
            uint32_t cslot = sbase + OFF_PAN + (uint32_t)((2 * t + p) & 3) * PAN_BYTES;
            int kp_base = (p < 2) ? (512 + p * 64) : ((p - 2) * 64);
            compute_panel(cslot, u_wt, kp_base, bp, np, kc, acc);
        }

        // Fold k-parity, reduce over the 4 k-lanes (xor 8, 16).
        float v[64];
#pragma unroll
        for (int i = 0; i < 64; ++i) {
            float lo, hi; UNPK(lo, hi, acc[i]);
            v[i] = lo + hi;
        }
#pragma unroll
        for (int r = 8; r <= 16; r <<= 1)
#pragma unroll
            for (int i = 0; i < 64; ++i)
                v[i] += __shfl_xor_sync(0xffffffffu, v[i], r);

        // Lanes 0-7 (pos = bp*4+... = lane) write partials: red[warp][pos*68 + e].
        if (lane < 8) {
            float* rb = red_f + warp * 544 + lane * 68;
#pragma unroll
            for (int i = 0; i < 64; i += 4)
                *(float4*)(rb + i) = make_float4(v[i], v[i + 1], v[i + 2], v[i + 3]);
        }
        __syncthreads();

        // Cross-warp sum + bias + tanh; write hstates + paired-transposed g_hx.
        float* hout   = hstates + (size_t)(t + 1) * (BB * HH);
        float* hx_dst = g_hx[(t + 1) & 1];
#pragma unroll
        for (int rr = 0; rr < 2; ++rr) {
            int o   = tid + rr * NTHREADS;    // 0..511
            int pos = o >> 6, e = o & 63;
            int ri  = pos * 68 + e;
            int nl  = (pos & 3) * 8 + (e & 7);        // n_local 0..31
            int bl  = ((pos >> 2) & 1) * 8 + (e >> 3); // b_local 0..15
            float s = bias_s[nl];
#pragma unroll
            for (int w = 0; w < 8; ++w) s += red_f[w * 544 + ri];
            float hv = tanhf(s);
            int bgl = b0 + bl, ngl = n0 + nl;
            hout[(size_t)bgl * HH + ngl] = hv;
            hx_dst[((ngl >> 1) * 128) + bgl * 2 + (ngl & 1)] = hv;
        }

        grid_barrier(base_gen, bstep++);
    }
    cp_wait<0>();
}

// ---------------- x transpose: x[b][t][k] -> g_xt[t][kp][b][2] ----------------
__global__ void transpose_x_kernel(const float* __restrict__ x) {
    __shared__ float tile[32][33];
    int k0 = blockIdx.x * 32, b0 = blockIdx.y * 32, t = blockIdx.z;
    int tx = threadIdx.x, ty = threadIdx.y;
#pragma unroll
    for (int i = 0; i < 4; ++i) {
        int b = b0 + ty + i * 8;
        tile[ty + i * 8][tx] = x[(size_t)b * (SS * II) + (size_t)t * II + k0 + tx];
    }
    __syncthreads();
#pragma unroll
    for (int i = 0; i < 4; ++i) {
        int k = k0 + ty + i * 8;
        int b = b0 + tx;
        g_xt[(size_t)t * 16384 + (size_t)(k >> 1) * 128 + b * 2 + (k & 1)] =
            tile[tx][ty + i * 8];
    }
}

// ---------------- init: zero h0 ----------------
__global__ void init_zero_kernel(float* __restrict__ hstates) {
    int i = blockIdx.x * blockDim.x + threadIdx.x;
    if (i < BB * HH) {
        hstates[i] = 0.f;
        g_hx[0][i] = 0.f;
    }
}

// ---------------- final FC ----------------
__global__ void __launch_bounds__(NTHREADS)
fc_kernel(const float* __restrict__ hlast,
          const float* __restrict__ fcw,
          const float* __restrict__ fcb,
          float* __restrict__ out)
{
    __shared__ float hrow[HH];
    int b = blockIdx.x;
    for (int i = threadIdx.x; i < HH; i += NTHREADS)
        hrow[i] = hlast[(size_t)b * HH + i];
    __syncthreads();

    int o = threadIdx.x;
    const float* w = fcw + (size_t)o * HH;
    float acc = 0.f;
#pragma unroll 4
    for (int k = 0; k < HH; k += 4) {
        float4 wv = *(const float4*)(w + k);
        acc = fmaf(hrow[k],     wv.x,
              fmaf(hrow[k + 1], wv.y,
              fmaf(hrow[k + 2], wv.z,
              fmaf(hrow[k + 3], wv.w, acc))));
    }
    out[(size_t)b * OO + o] = acc + fcb[o];
}

extern "C" void kernel_launch(void* const* d_in, const int* in_sizes, int n_in,
                              void* d_out, int out_size) {
    const float* x    = (const float*)d_in[0];   // [64,512,256]
    const float* wih  = (const float*)d_in[1];   // [1024,256]
    const float* whh  = (const float*)d_in[2];   // [1024,1024]
    const float* bias = (const float*)d_in[3];   // [1024]
    const float* fcw  = (const float*)d_in[4];   // [256,1024]
    const float* fcb  = (const float*)d_in[5];   // [256]

    float* out     = (float*)d_out;              // output [64,256]
    float* hstates = out + (size_t)BB * OO;      // hidden_states [513,64,1024]

    cudaFuncSetAttribute(rnn_persistent_kernel,
                         cudaFuncAttributeMaxDynamicSharedMemorySize, SMEM_BYTES);

    transpose_x_kernel<<<dim3(II / 32, BB / 32, SS), dim3(32, 8)>>>(x);
    init_zero_kernel<<<(BB * HH + 255) / 256, 256>>>(hstates);

    rnn_persistent_kernel<<<NBLOCKS, NTHREADS, SMEM_BYTES>>>(wih, whh, bias, hstates);

    const float* hlast = hstates + (size_t)SS * (BB * HH);
    fc_kernel<<<BB, NTHREADS>>>(hlast, fcw, fcb, out);
}

// round 12
// speedup vs baseline: 1.7743x; 1.7743x over previous
#include <cuda_runtime.h>
#include <cstdint>

#define NBLOCKS   128
#define NTHREADS  256
#define BB        64
#define HH        1024
#define II        256
#define SS        512
#define OO        256
#define SI        (SS * II)

// ---------------- grid barrier ----------------
__device__ unsigned g_bar_count = 0;
__device__ unsigned g_bar_gen   = 0;

__device__ __forceinline__ void grid_barrier(unsigned base_gen, unsigned step) {
    __syncthreads();
    if (threadIdx.x == 0) {
        __threadfence();
        unsigned prev = atomicAdd(&g_bar_count, 1u);
        if (prev == NBLOCKS - 1) {
            g_bar_count = 0;
            __threadfence();
            atomicAdd(&g_bar_gen, 1u);
        } else {
            while (*(volatile unsigned*)&g_bar_gen - base_gen < step) { }
        }
        __threadfence();
    }
    __syncthreads();
}

// ---------------- cp.async ----------------
__device__ __forceinline__ void cp_async16(uint32_t dst, const void* src) {
    asm volatile("cp.async.cg.shared.global [%0], [%1], 16;" :: "r"(dst), "l"(src));
}
__device__ __forceinline__ void cp_commit() {
    asm volatile("cp.async.commit_group;" ::: "memory");
}
template <int N>
__device__ __forceinline__ void cp_wait() {
    asm volatile("cp.async.wait_group %0;" :: "n"(N) : "memory");
}

// ---------------- tf32 helpers ----------------
__device__ __forceinline__ uint32_t f2tf32(float f) {
    uint32_t u;
    asm("cvt.rna.tf32.f32 %0, %1;" : "=r"(u) : "f"(f));
    return u;
}

// mma.sync m16n8k8 tf32: D += A(16x8, row) * B(8x8, col), fp32 accum.
__device__ __forceinline__ void mma_tf32(float* c,
                                         uint32_t a0, uint32_t a1, uint32_t a2, uint32_t a3,
                                         uint32_t b0, uint32_t b1) {
    asm volatile(
        "mma.sync.aligned.m16n8k8.row.col.f32.tf32.tf32.f32 "
        "{%0,%1,%2,%3},{%4,%5,%6,%7},{%8,%9},{%0,%1,%2,%3};"
        : "+f"(c[0]), "+f"(c[1]), "+f"(c[2]), "+f"(c[3])
        : "r"(a0), "r"(a1), "r"(a2), "r"(a3), "r"(b0), "r"(b1));
}

// ---------------- smem layout (bytes) ----------------
//   w_s    : 1280 k x 32 n x 4   = 163840  ([k][n] with col rotation by (k&3)*8)
//   panels : 4 x (16 x 132 x 4)  =  33792  ([b][k 0..127], row pad 132 floats)
//   red    : 8 x 544 x 4         =  17408  ([warp][b*34 + n])
//   bias   : 128
static constexpr int OFF_W    = 0;
static constexpr int OFF_PAN  = 163840;
static constexpr int PAN_BYTES = 16 * 132 * 4;            // 8448
static constexpr int OFF_RED  = OFF_PAN + 4 * PAN_BYTES;  // 197632
static constexpr int OFF_BIAS = OFF_RED + 8 * 544 * 4;    // 215040
static constexpr int SMEM_BYTES = OFF_BIAS + 128;         // 215168

// Stage one 16-row x 128-float panel (512 x 16B chunks, 2 per thread).
__device__ __forceinline__ void stage_panel(const float* __restrict__ srcRowBase,
                                            int rowStrideFloats, uint32_t dstBase) {
#pragma unroll
    for (int j = 0; j < 2; ++j) {
        int e   = threadIdx.x + j * NTHREADS;   // 0..511
        int row = e >> 5;                       // b 0..15
        int cc  = e & 31;                       // 16B chunk in row
        cp_async16(dstBase + (uint32_t)(row * 528 + cc * 16),
                   srcRowBase + (size_t)row * rowStrideFloats + cc * 4);
    }
    cp_commit();
}

__global__ void __launch_bounds__(NTHREADS, 1)
rnn_tc_kernel(const float* __restrict__ x,
              const float* __restrict__ wih,
              const float* __restrict__ whh,
              const float* __restrict__ bias,
              float* __restrict__ hstates)   // [S+1][B][H]
{
    extern __shared__ float smem_f[];
    char* smem = (char*)smem_f;
    const uint32_t sbase = (uint32_t)__cvta_generic_to_shared(smem);
    uint32_t* w_u   = (uint32_t*)(smem + OFF_W);
    float*    red_f = (float*)(smem + OFF_RED);
    float*    bias_s = (float*)(smem + OFF_BIAS);

    const int tid  = threadIdx.x;
    const int lane = tid & 31;
    const int warp = tid >> 5;
    const int lq   = lane >> 2;      // 0..7  (b row / n col within tile)
    const int lr   = lane & 3;       // 0..3  (k within k4)
    const int ng   = blockIdx.x & 31;            // 32 n-groups of 32
    const int bg   = blockIdx.x >> 5;            // 4 b-groups of 16
    const int n0   = ng * 32;
    const int b0   = bg * 16;

    // Fill W: w(k, n0+n) -> w_u[k*32 + ((n + 8*(k&3)) & 31)], tf32-rounded.
    for (int i = tid; i < 32 * 1280; i += NTHREADS) {
        int n = i / 1280;
        int k = i - n * 1280;
        float v = (k < HH) ? whh[(size_t)(n0 + n) * HH + k]
                           : wih[(size_t)(n0 + n) * II + (k - HH)];
        w_u[k * 32 + ((n + 8 * (k & 3)) & 31)] = f2tf32(v);
    }
    if (tid < 32) bias_s[tid] = bias[n0 + tid];

    unsigned base_gen = *(volatile unsigned*)&g_bar_gen;

    // Prologue: stage the two x panels for t=0 into slots 0, 1.
    stage_panel(x + (size_t)b0 * SI + 0 * 128, SI, sbase + OFF_PAN + 0 * PAN_BYTES);
    stage_panel(x + (size_t)b0 * SI + 1 * 128, SI, sbase + OFF_PAN + 1 * PAN_BYTES);
    __syncthreads();   // w_s / bias visible

    unsigned bstep = 1;
    const int col0 = (lq + 8 * lr) & 31;   // rotated B column base (lane-constant)

#pragma unroll 1
    for (int t = 0; t < SS; ++t) {
        float C[16];
#pragma unroll
        for (int i = 0; i < 16; ++i) C[i] = 0.f;

        const float* hsrc = hstates + (size_t)t * (BB * HH) + (size_t)b0 * HH;

        // Panels: p0,p1 = x (k base 1024,1152); p2..p9 = h (k base 0..896).
#pragma unroll 1
        for (int p = 0; p < 10; ++p) {
            int next = p + 2;
            uint32_t nslot = sbase + OFF_PAN + (uint32_t)((2 * t + next) & 3) * PAN_BYTES;
            if (next < 10) {
                stage_panel(hsrc + (next - 2) * 128, HH, nslot);
            } else {
                int tn = (t + 1 < SS) ? (t + 1) : t;
                stage_panel(x + (size_t)b0 * SI + (size_t)tn * II + (next - 10) * 128,
                            SI, nslot);
            }
            cp_wait<2>();
            __syncthreads();

            const float* panf = (const float*)(smem + OFF_PAN
                                + (size_t)((2 * t + p) & 3) * PAN_BYTES);
            int kp_base = (p < 2) ? (1024 + p * 128) : ((p - 2) * 128);

#pragma unroll
            for (int it = 0; it < 2; ++it) {
                int kb = (warp << 4) + (it << 3);      // panel-local k base
                const float* ap = panf + lq * 132 + kb + lr;
                uint32_t a0 = f2tf32(ap[0]);
                uint32_t a1 = f2tf32(ap[8 * 132]);
                uint32_t a2 = f2tf32(ap[4]);
                uint32_t a3 = f2tf32(ap[8 * 132 + 4]);
                const uint32_t* wb = w_u + (kp_base + kb + lr) * 32;
#pragma unroll
                for (int nt = 0; nt < 4; ++nt) {
                    int c = (col0 + nt * 8) & 31;
                    mma_tf32(C + nt * 4, a0, a1, a2, a3, wb[c], wb[128 + c]);
                }
            }
        }

        // Epilogue: warp partials -> red[warp][b*34 + n] (float2, 8B aligned).
        {
            float* rb = red_f + warp * 544;
#pragma unroll
            for (int nt = 0; nt < 4; ++nt) {
                int n = nt * 8 + 2 * lr;
                *(float2*)(rb + lq * 34 + n)       = make_float2(C[nt * 4 + 0], C[nt * 4 + 1]);
                *(float2*)(rb + (lq + 8) * 34 + n) = make_float2(C[nt * 4 + 2], C[nt * 4 + 3]);
            }
        }
        __syncthreads();

        // Sum 8 warps + bias, tanh, write hstates[t+1].
        {
            float* hout = hstates + (size_t)(t + 1) * (BB * HH);
#pragma unroll
            for (int rr = 0; rr < 2; ++rr) {
                int o = tid + rr * NTHREADS;      // 0..511
                int b = o >> 5, n = o & 31;
                float s = bias_s[n];
#pragma unroll
                for (int w = 0; w < 8; ++w) s += red_f[w * 544 + b * 34 + n];
                hout[(size_t)(b0 + b) * HH + n0 + n] = tanhf(s);
            }
        }

        grid_barrier(base_gen, bstep++);
    }
    cp_wait<0>();
}

// ---------------- init: zero h0 ----------------
__global__ void init_zero_kernel(float* __restrict__ hstates) {
    int i = blockIdx.x * blockDim.x + threadIdx.x;
    if (i < BB * HH) hstates[i] = 0.f;
}

// ---------------- final FC ----------------
__global__ void __launch_bounds__(256)
fc_kernel(const float* __restrict__ hlast,
          const float* __restrict__ fcw,
          const float* __restrict__ fcb,
          float* __restrict__ out)
{
    __shared__ float hrow[HH];
    int b = blockIdx.x;
    for (int i = threadIdx.x; i < HH; i += 256)
        hrow[i] = hlast[(size_t)b * HH + i];
    __syncthreads();

    int o = threadIdx.x;
    const float* w = fcw + (size_t)o * HH;
    float acc = 0.f;
#pragma unroll 4
    for (int k = 0; k < HH; k += 4) {
        float4 wv = *(const float4*)(w + k);
        acc = fmaf(hrow[k],     wv.x,
              fmaf(hrow[k + 1], wv.y,
              fmaf(hrow[k + 2], wv.z,
              fmaf(hrow[k + 3], wv.w, acc))));
    }
    out[(size_t)b * OO + o] = acc + fcb[o];
}

extern "C" void kernel_launch(void* const* d_in, const int* in_sizes, int n_in,
                              void* d_out, int out_size) {
    const float* x    = (const float*)d_in[0];   // [64,512,256]
    const float* wih  = (const float*)d_in[1];   // [1024,256]
    const float* whh  = (const float*)d_in[2];   // [1024,1024]
    const float* bias = (const float*)d_in[3];   // [1024]
    const float* fcw  = (const float*)d_in[4];   // [256,1024]
    const float* fcb  = (const float*)d_in[5];   // [256]

    float* out     = (float*)d_out;              // output [64,256]
    float* hstates = out + (size_t)BB * OO;      // hidden_states [513,64,1024]

    cudaFuncSetAttribute(rnn_tc_kernel,
                         cudaFuncAttributeMaxDynamicSharedMemorySize, SMEM_BYTES);

    init_zero_kernel<<<(BB * HH + 255) / 256, 256>>>(hstates);
    rnn_tc_kernel<<<NBLOCKS, NTHREADS, SMEM_BYTES>>>(x, wih, whh, bias, hstates);

    const float* hlast = hstates + (size_t)SS * (BB * HH);
    fc_kernel<<<BB, 256>>>(hlast, fcw, fcb, out);
}